// round 4
// baseline (speedup 1.0000x reference)
#include <cuda_runtime.h>
#include <cstdint>

#define NQ   4
#define DIM  16
#define NL   2
#define EDIM 512
#define E4   128                 // float4 per token row
#define NTHREADS 128
#define NWARPS 4
#define TOK_PER_WARP 4
#define TOK_PER_BLOCK 16
#define NTOKENS (512*128)

__device__ __forceinline__ uint32_t smem_u32(const void* p) {
    return (uint32_t)__cvta_generic_to_shared(p);
}
__device__ __forceinline__ void cp_async16(uint32_t dst, const void* src) {
    asm volatile("cp.async.cg.shared.global [%0], [%1], 16;" :: "r"(dst), "l"(src));
}
__device__ __forceinline__ void cp_commit() {
    asm volatile("cp.async.commit_group;");
}
__device__ __forceinline__ void cp_wait_all() {
    asm volatile("cp.async.wait_group 0;" ::: "memory");
}

__global__ __launch_bounds__(NTHREADS)
void qlayer_fused(const float* __restrict__ x,
                  const float* __restrict__ qw,
                  const float* __restrict__ Wq,
                  const float* __restrict__ bq,
                  const float* __restrict__ Wc,
                  const float* __restrict__ bc,
                  float* __restrict__ out)
{
    __shared__ float4 sWq[NQ][E4];                      // 8 KB
    __shared__ float4 sx[NWARPS][TOK_PER_WARP][E4];     // 32 KB staging for x
    __shared__ float2 sdiag[NL][DIM];                   // fused CRZ-ring diagonal
    __shared__ float2 srys[NL][NQ];
    __shared__ float  sbq[NQ];
    __shared__ float4 sqout[TOK_PER_BLOCK];

    const int tid  = threadIdx.x;
    const int lane = tid & 31;
    const int warp = tid >> 5;
    const int tokW = blockIdx.x * TOK_PER_BLOCK + warp * TOK_PER_WARP;

    // ---- Fire all x loads FIRST (register-free MLP via cp.async) ----
    {
        uint32_t dst0 = smem_u32(&sx[warp][0][lane]);
        const float4* src0 = &((const float4*)x)[(size_t)tokW * E4 + lane];
        #pragma unroll
        for (int t = 0; t < TOK_PER_WARP; t++)
            #pragma unroll
            for (int c = 0; c < 4; c++)
                cp_async16(dst0 + (uint32_t)(t*E4 + c*32)*16,
                           src0 + (size_t)t*E4 + c*32);
        cp_commit();
    }

    // ---- Stage Wq + circuit constants while x streams in ----
    for (int i = tid; i < NQ*E4; i += NTHREADS)
        ((float4*)sWq)[i] = ((const float4*)Wq)[i];
    if (tid < NQ) sbq[tid] = bq[tid];

    if (tid < NL*DIM) {           // combined CRZ-ring diagonal (all CRZ are diagonal)
        int l = tid >> 4, k = tid & 15;
        float ang = 0.f;
        #pragma unroll
        for (int i = 0; i < NQ; i++) {
            int cb = (k >> (NQ-1-i)) & 1;
            int tb = (k >> (NQ-1-((i+1)&(NQ-1)))) & 1;
            if (cb) ang += 0.5f * qw[l*2*NQ + i] * (float)(2*tb - 1);
        }
        float sn, cs; sincosf(ang, &sn, &cs);
        sdiag[l][k] = make_float2(cs, sn);
    }
    if (tid >= 32 && tid < 32 + NL*NQ) {
        int t = tid - 32, l = t >> 2, i = t & 3;
        float sn, cs; sincosf(0.5f * qw[l*2*NQ + NQ + i], &sn, &cs);
        srys[l][i] = make_float2(cs, sn);
    }
    __syncthreads();   // weights/constants visible to all

    const float bq0 = sbq[0], bq1 = sbq[1], bq2 = sbq[2], bq3 = sbq[3];

    // ---- Phase 1: q_in for 4 tokens/warp from smem-staged x ----
    cp_wait_all();     // per-lane data: each lane reads exactly what it copied

    float v16[16];
    #pragma unroll
    for (int i = 0; i < 16; i++) v16[i] = 0.f;

    #pragma unroll
    for (int chunk = 0; chunk < 4; chunk++) {
        const int j4 = chunk*32 + lane;
        const float4 w0 = sWq[0][j4], w1 = sWq[1][j4];
        const float4 w2 = sWq[2][j4], w3 = sWq[3][j4];
        #pragma unroll
        for (int t = 0; t < TOK_PER_WARP; t++) {
            float4 xv = sx[warp][t][j4];
            v16[4*t+0] += xv.x*w0.x + xv.y*w0.y + xv.z*w0.z + xv.w*w0.w;
            v16[4*t+1] += xv.x*w1.x + xv.y*w1.y + xv.z*w1.z + xv.w*w1.w;
            v16[4*t+2] += xv.x*w2.x + xv.y*w2.y + xv.z*w2.z + xv.w*w2.w;
            v16[4*t+3] += xv.x*w3.x + xv.y*w3.y + xv.z*w3.z + xv.w*w3.w;
        }
    }

    // multi-value tree reduction: 16 values -> 1 per lane
    float v8[8];
    {
        const bool hi = (lane & 16) != 0;
        #pragma unroll
        for (int i = 0; i < 8; i++) {
            float mine = hi ? v16[i+8] : v16[i];
            float send = hi ? v16[i]   : v16[i+8];
            v8[i] = mine + __shfl_xor_sync(0xffffffffu, send, 16);
        }
    }
    float v4[4];
    {
        const bool hi = (lane & 8) != 0;
        #pragma unroll
        for (int i = 0; i < 4; i++) {
            float mine = hi ? v8[i+4] : v8[i];
            float send = hi ? v8[i]   : v8[i+4];
            v4[i] = mine + __shfl_xor_sync(0xffffffffu, send, 8);
        }
    }
    float v2[2];
    {
        const bool hi = (lane & 4) != 0;
        #pragma unroll
        for (int i = 0; i < 2; i++) {
            float m2 = hi ? v4[i+2] : v4[i];
            float s2 = hi ? v4[i]   : v4[i+2];
            v2[i] = m2 + __shfl_xor_sync(0xffffffffu, s2, 4);
        }
    }
    float v1;
    {
        const bool hi = (lane & 2) != 0;
        float mine = hi ? v2[1] : v2[0];
        float send = hi ? v2[0] : v2[1];
        v1 = mine + __shfl_xor_sync(0xffffffffu, send, 2);
    }
    v1 += __shfl_xor_sync(0xffffffffu, v1, 1);
    // lane L holds (t = L>>3, q = 2*((L>>2)&1) + ((L>>1)&1)); gather tokens to lanes 0..3
    const int tl = lane & 3;
    float gx = __shfl_sync(0xffffffffu, v1, 8*tl + 0);
    float gy = __shfl_sync(0xffffffffu, v1, 8*tl + 2);
    float gz = __shfl_sync(0xffffffffu, v1, 8*tl + 4);
    float gw = __shfl_sync(0xffffffffu, v1, 8*tl + 6);
    float4 qin = make_float4(gx + bq0, gy + bq1, gz + bq2, gw + bq3);

    // ---- Phase 2: 4-qubit circuit on lanes 0..3 (one token per lane) ----
    if (lane < TOK_PER_WARP) {
        float c[4], s[4];
        __sincosf(0.5f*qin.x, &s[0], &c[0]);
        __sincosf(0.5f*qin.y, &s[1], &c[1]);
        __sincosf(0.5f*qin.z, &s[2], &c[2]);
        __sincosf(0.5f*qin.w, &s[3], &c[3]);

        float2 st[DIM];
        #pragma unroll
        for (int k = 0; k < DIM; k++) {
            float m = 1.f; int p = 0;
            #pragma unroll
            for (int w = 0; w < NQ; w++) {
                if ((k >> (NQ-1-w)) & 1) { m *= s[w]; p++; }
                else                     { m *= c[w]; }
            }
            float re, im;
            switch (p & 3) {
                case 0:  re =  m; im = 0.f; break;
                case 1:  re = 0.f; im = -m; break;
                case 2:  re = -m; im = 0.f; break;
                default: re = 0.f; im =  m; break;
            }
            st[k] = make_float2(re, im);
        }

        #pragma unroll
        for (int l = 0; l < NL; l++) {
            #pragma unroll
            for (int k = 0; k < DIM; k++) {
                float2 d = sdiag[l][k];
                float re = st[k].x*d.x - st[k].y*d.y;
                float im = st[k].x*d.y + st[k].y*d.x;
                st[k].x = re; st[k].y = im;
            }
            #pragma unroll
            for (int i = 0; i < NQ; i++) {
                float2 cs = srys[l][i];
                const int S = 1 << (NQ-1-i);
                #pragma unroll
                for (int k = 0; k < DIM; k++) {
                    if (k & S) continue;
                    float2 a0 = st[k], a1 = st[k|S];
                    st[k].x   = cs.x*a0.x - cs.y*a1.x;
                    st[k].y   = cs.x*a0.y - cs.y*a1.y;
                    st[k|S].x = cs.y*a0.x + cs.x*a1.x;
                    st[k|S].y = cs.y*a0.y + cs.x*a1.y;
                }
            }
        }

        float z0=0.f, z1=0.f, z2=0.f, z3=0.f;
        #pragma unroll
        for (int k = 0; k < DIM; k++) {
            float p = st[k].x*st[k].x + st[k].y*st[k].y;
            z0 += (k & 8) ? -p : p;
            z1 += (k & 4) ? -p : p;
            z2 += (k & 2) ? -p : p;
            z3 += (k & 1) ? -p : p;
        }
        sqout[warp*TOK_PER_WARP + lane] = make_float4(z0, z1, z2, z3);
    }
    __syncwarp();

    // ---- Phase 3: out = q_out . Wc^T + bc ; Wc/bc straight from L1 ----
    const float4* Wc4 = (const float4*)Wc;   // row e = 4 floats over q
    const float4* bc4 = (const float4*)bc;
    #pragma unroll 1
    for (int chunk = 0; chunk < 4; chunk++) {
        const int e4 = chunk*32 + lane;          // output float4 index
        const float4 r0 = __ldg(&Wc4[e4*4 + 0]);
        const float4 r1 = __ldg(&Wc4[e4*4 + 1]);
        const float4 r2 = __ldg(&Wc4[e4*4 + 2]);
        const float4 r3 = __ldg(&Wc4[e4*4 + 3]);
        const float4 b  = __ldg(&bc4[e4]);
        #pragma unroll
        for (int m = 0; m < TOK_PER_WARP; m++) {
            float4 qo = sqout[warp*TOK_PER_WARP + m];   // LDS broadcast
            float4 o;
            o.x = b.x + qo.x*r0.x + qo.y*r0.y + qo.z*r0.z + qo.w*r0.w;
            o.y = b.y + qo.x*r1.x + qo.y*r1.y + qo.z*r1.z + qo.w*r1.w;
            o.z = b.z + qo.x*r2.x + qo.y*r2.y + qo.z*r2.z + qo.w*r2.w;
            o.w = b.w + qo.x*r3.x + qo.y*r3.y + qo.z*r3.z + qo.w*r3.w;
            __stcs(&((float4*)out)[(size_t)(tokW + m)*E4 + e4], o);
        }
    }
}

extern "C" void kernel_launch(void* const* d_in, const int* in_sizes, int n_in,
                              void* d_out, int out_size) {
    const float* x  = (const float*)d_in[0];
    const float* qw = (const float*)d_in[1];
    const float* Wq = (const float*)d_in[2];
    const float* bq = (const float*)d_in[3];
    const float* Wc = (const float*)d_in[4];
    const float* bc = (const float*)d_in[5];
    float* out = (float*)d_out;

    dim3 grid(NTOKENS / TOK_PER_BLOCK);   // 4096 blocks x 128 threads
    qlayer_fused<<<grid, NTHREADS>>>(x, qw, Wq, bq, Wc, bc, out);
}

// round 5
// speedup vs baseline: 1.1497x; 1.1497x over previous
#include <cuda_runtime.h>
#include <cstdint>

#define NQ   4
#define DIM  16
#define NL   2
#define EDIM 512
#define E4   128                  // float4 per token row
#define NTHREADS 128
#define NWARPS 4
#define TOK_PER_TILE 4
#define NTOKENS (512*128)
#define NTILES (NTOKENS / TOK_PER_TILE)    // 16384
#define GRID 608                            // ~4 blocks/SM, one balanced wave

__global__ __launch_bounds__(NTHREADS)
void qlayer_fused(const float* __restrict__ x,
                  const float* __restrict__ qw,
                  const float* __restrict__ Wq,
                  const float* __restrict__ bq,
                  const float* __restrict__ Wc,
                  const float* __restrict__ bc,
                  float* __restrict__ out)
{
    __shared__ float4 sWq[NQ][E4];     // 8 KB
    __shared__ float4 sWcT[NQ][E4];    // 8 KB, Wc transposed [q][e4]
    __shared__ float4 sbc4[E4];        // 2 KB
    __shared__ float2 sdiag[NL][DIM];  // fused CRZ-ring diagonal
    __shared__ float2 srys[NL][NQ];
    __shared__ float  sbq[NQ];

    const int tid  = threadIdx.x;
    const int lane = tid & 31;
    const int warp = tid >> 5;

    // ---- Stage weights / constants into shared (once per block) ----
    for (int i = tid; i < NQ*E4; i += NTHREADS)
        ((float4*)sWq)[i] = ((const float4*)Wq)[i];
    {
        float* f = (float*)sWcT;
        for (int e = tid; e < EDIM; e += NTHREADS) {
            float4 r = ((const float4*)Wc)[e];
            f[0*EDIM+e] = r.x; f[1*EDIM+e] = r.y;
            f[2*EDIM+e] = r.z; f[3*EDIM+e] = r.w;
        }
    }
    for (int i = tid; i < E4; i += NTHREADS)
        sbc4[i] = ((const float4*)bc)[i];
    if (tid < NQ) sbq[tid] = bq[tid];

    if (tid < NL*DIM) {                // combined CRZ-ring diagonal
        int l = tid >> 4, k = tid & 15;
        float ang = 0.f;
        #pragma unroll
        for (int i = 0; i < NQ; i++) {
            int cb = (k >> (NQ-1-i)) & 1;
            int tb = (k >> (NQ-1-((i+1)&(NQ-1)))) & 1;
            if (cb) ang += 0.5f * qw[l*2*NQ + i] * (float)(2*tb - 1);
        }
        float sn, cs; sincosf(ang, &sn, &cs);
        sdiag[l][k] = make_float2(cs, sn);
    }
    if (tid >= 32 && tid < 32 + NL*NQ) {
        int t = tid - 32, l = t >> 2, i = t & 3;
        float sn, cs; sincosf(0.5f * qw[l*2*NQ + NQ + i], &sn, &cs);
        srys[l][i] = make_float2(cs, sn);
    }
    __syncthreads();

    const float bq0 = sbq[0], bq1 = sbq[1], bq2 = sbq[2], bq3 = sbq[3];
    const float4* __restrict__ x4 = (const float4*)x;
    float4* __restrict__ out4 = (float4*)out;

    const int gw     = blockIdx.x * NWARPS + warp;     // global warp id
    const int stride = GRID * NWARPS;                  // 2432

    float4 xbuf[16];                   // 4 tokens x 4 chunks, the pipeline buffer

    // ---- Prologue: load first tile ----
    int tile = gw;
    if (tile < NTILES) {
        const size_t base = (size_t)tile * TOK_PER_TILE * E4 + lane;
        #pragma unroll
        for (int t = 0; t < 4; t++)
            #pragma unroll
            for (int c = 0; c < 4; c++)
                xbuf[t*4+c] = __ldcs(&x4[base + (size_t)t*E4 + c*32]);
    }

    #pragma unroll 1
    for (; tile < NTILES; tile += stride) {
        // ---- Consume buffer: partial dot products (frees xbuf) ----
        float v16[16];
        #pragma unroll
        for (int i = 0; i < 16; i++) v16[i] = 0.f;
        #pragma unroll
        for (int c = 0; c < 4; c++) {
            const int j4 = c*32 + lane;
            const float4 w0 = sWq[0][j4], w1 = sWq[1][j4];
            const float4 w2 = sWq[2][j4], w3 = sWq[3][j4];
            #pragma unroll
            for (int t = 0; t < 4; t++) {
                float4 xv = xbuf[t*4+c];
                v16[4*t+0] += xv.x*w0.x + xv.y*w0.y + xv.z*w0.z + xv.w*w0.w;
                v16[4*t+1] += xv.x*w1.x + xv.y*w1.y + xv.z*w1.z + xv.w*w1.w;
                v16[4*t+2] += xv.x*w2.x + xv.y*w2.y + xv.z*w2.z + xv.w*w2.w;
                v16[4*t+3] += xv.x*w3.x + xv.y*w3.y + xv.z*w3.z + xv.w*w3.w;
            }
        }

        // ---- Prefetch next tile NOW: in flight during shfl+circuit+store ----
        const int nxt = tile + stride;
        if (nxt < NTILES) {
            const size_t base = (size_t)nxt * TOK_PER_TILE * E4 + lane;
            #pragma unroll
            for (int t = 0; t < 4; t++)
                #pragma unroll
                for (int c = 0; c < 4; c++)
                    xbuf[t*4+c] = __ldcs(&x4[base + (size_t)t*E4 + c*32]);
        }

        // ---- Tree reduction: 16 values -> 1 per lane ----
        float v8[8];
        {
            const bool hi = (lane & 16) != 0;
            #pragma unroll
            for (int i = 0; i < 8; i++) {
                float mine = hi ? v16[i+8] : v16[i];
                float send = hi ? v16[i]   : v16[i+8];
                v8[i] = mine + __shfl_xor_sync(0xffffffffu, send, 16);
            }
        }
        float v4[4];
        {
            const bool hi = (lane & 8) != 0;
            #pragma unroll
            for (int i = 0; i < 4; i++) {
                float mine = hi ? v8[i+4] : v8[i];
                float send = hi ? v8[i]   : v8[i+4];
                v4[i] = mine + __shfl_xor_sync(0xffffffffu, send, 8);
            }
        }
        float v2[2];
        {
            const bool hi = (lane & 4) != 0;
            #pragma unroll
            for (int i = 0; i < 2; i++) {
                float m2 = hi ? v4[i+2] : v4[i];
                float s2 = hi ? v4[i]   : v4[i+2];
                v2[i] = m2 + __shfl_xor_sync(0xffffffffu, s2, 4);
            }
        }
        float v1;
        {
            const bool hi = (lane & 2) != 0;
            float mine = hi ? v2[1] : v2[0];
            float send = hi ? v2[0] : v2[1];
            v1 = mine + __shfl_xor_sync(0xffffffffu, send, 2);
        }
        v1 += __shfl_xor_sync(0xffffffffu, v1, 1);
        // lane L holds (t = L>>3, q = 2*((L>>2)&1)+((L>>1)&1)); gather tokens -> lanes 0..3
        const int tl = lane & 3;
        float gx = __shfl_sync(0xffffffffu, v1, 8*tl + 0);
        float gy = __shfl_sync(0xffffffffu, v1, 8*tl + 2);
        float gz = __shfl_sync(0xffffffffu, v1, 8*tl + 4);
        float gw_ = __shfl_sync(0xffffffffu, v1, 8*tl + 6);

        // ---- Circuit on lanes 0..3 (one token per lane) ----
        float z0 = 0.f, z1 = 0.f, z2 = 0.f, z3 = 0.f;
        if (lane < TOK_PER_TILE) {
            float4 qin = make_float4(gx + bq0, gy + bq1, gz + bq2, gw_ + bq3);
            float c[4], s[4];
            __sincosf(0.5f*qin.x, &s[0], &c[0]);
            __sincosf(0.5f*qin.y, &s[1], &c[1]);
            __sincosf(0.5f*qin.z, &s[2], &c[2]);
            __sincosf(0.5f*qin.w, &s[3], &c[3]);

            float2 st[DIM];
            #pragma unroll
            for (int k = 0; k < DIM; k++) {
                float m = 1.f; int p = 0;
                #pragma unroll
                for (int w = 0; w < NQ; w++) {
                    if ((k >> (NQ-1-w)) & 1) { m *= s[w]; p++; }
                    else                     { m *= c[w]; }
                }
                float re, im;
                switch (p & 3) {
                    case 0:  re =  m; im = 0.f; break;
                    case 1:  re = 0.f; im = -m; break;
                    case 2:  re = -m; im = 0.f; break;
                    default: re = 0.f; im =  m; break;
                }
                st[k] = make_float2(re, im);
            }

            #pragma unroll
            for (int l = 0; l < NL; l++) {
                #pragma unroll
                for (int k = 0; k < DIM; k++) {
                    float2 d = sdiag[l][k];
                    float re = st[k].x*d.x - st[k].y*d.y;
                    float im = st[k].x*d.y + st[k].y*d.x;
                    st[k].x = re; st[k].y = im;
                }
                #pragma unroll
                for (int i = 0; i < NQ; i++) {
                    float2 cs = srys[l][i];
                    const int S = 1 << (NQ-1-i);
                    #pragma unroll
                    for (int k = 0; k < DIM; k++) {
                        if (k & S) continue;
                        float2 a0 = st[k], a1 = st[k|S];
                        st[k].x   = cs.x*a0.x - cs.y*a1.x;
                        st[k].y   = cs.x*a0.y - cs.y*a1.y;
                        st[k|S].x = cs.y*a0.x + cs.x*a1.x;
                        st[k|S].y = cs.y*a0.y + cs.x*a1.y;
                    }
                }
            }

            #pragma unroll
            for (int k = 0; k < DIM; k++) {
                float p = st[k].x*st[k].x + st[k].y*st[k].y;
                z0 += (k & 8) ? -p : p;
                z1 += (k & 4) ? -p : p;
                z2 += (k & 2) ? -p : p;
                z3 += (k & 1) ? -p : p;
            }
        }

        // ---- Phase 3: out = q_out . Wc^T + bc (q_out via shfl broadcast) ----
        const size_t obase = (size_t)tile * TOK_PER_TILE * E4;
        #pragma unroll
        for (int c = 0; c < 4; c++) {
            const int e4 = c*32 + lane;
            const float4 w0 = sWcT[0][e4], w1 = sWcT[1][e4];
            const float4 w2 = sWcT[2][e4], w3 = sWcT[3][e4];
            const float4 b  = sbc4[e4];
            #pragma unroll
            for (int m = 0; m < TOK_PER_TILE; m++) {
                float qx = __shfl_sync(0xffffffffu, z0, m);
                float qy = __shfl_sync(0xffffffffu, z1, m);
                float qz = __shfl_sync(0xffffffffu, z2, m);
                float qe = __shfl_sync(0xffffffffu, z3, m);
                float4 o;
                o.x = b.x + qx*w0.x + qy*w1.x + qz*w2.x + qe*w3.x;
                o.y = b.y + qx*w0.y + qy*w1.y + qz*w2.y + qe*w3.y;
                o.z = b.z + qx*w0.z + qy*w1.z + qz*w2.z + qe*w3.z;
                o.w = b.w + qx*w0.w + qy*w1.w + qz*w2.w + qe*w3.w;
                __stcs(&out4[obase + (size_t)m*E4 + e4], o);
            }
        }
    }
}

extern "C" void kernel_launch(void* const* d_in, const int* in_sizes, int n_in,
                              void* d_out, int out_size) {
    const float* x  = (const float*)d_in[0];
    const float* qw = (const float*)d_in[1];
    const float* Wq = (const float*)d_in[2];
    const float* bq = (const float*)d_in[3];
    const float* Wc = (const float*)d_in[4];
    const float* bc = (const float*)d_in[5];
    float* out = (float*)d_out;

    qlayer_fused<<<GRID, NTHREADS>>>(x, qw, Wq, bq, Wc, bc, out);
}

// round 6
// speedup vs baseline: 1.1619x; 1.0106x over previous
#include <cuda_runtime.h>
#include <cstdint>

#define NQ   4
#define DIM  16
#define NL   2
#define EDIM 512
#define E4   128                  // float4 per token row
#define NTHREADS 128
#define NWARPS 4
#define TOK_PER_TILE 4
#define NTOKENS (512*128)
#define NTILES (NTOKENS / TOK_PER_TILE)    // 16384
#define GRID 592                            // 4 blocks/SM exactly (148 SMs)

typedef unsigned long long ull;

__device__ __forceinline__ ull pack2(float lo, float hi) {
    ull r; asm("mov.b64 %0, {%1,%2};" : "=l"(r) : "f"(lo), "f"(hi)); return r;
}
__device__ __forceinline__ ull dup2(float v) {
    ull r; asm("mov.b64 %0, {%1,%1};" : "=l"(r) : "f"(v)); return r;
}
__device__ __forceinline__ void unpack2(ull p, float& lo, float& hi) {
    asm("mov.b64 {%0,%1}, %2;" : "=f"(lo), "=f"(hi) : "l"(p));
}
__device__ __forceinline__ ull ffma2(ull a, ull b, ull c) {
    ull d; asm("fma.rn.f32x2 %0, %1, %2, %3;" : "=l"(d) : "l"(a), "l"(b), "l"(c));
    return d;
}
__device__ __forceinline__ void stcs2x64(void* p, ull a, ull b) {
    asm volatile("st.global.cs.v2.b64 [%0], {%1,%2};" :: "l"(p), "l"(a), "l"(b) : "memory");
}

__global__ __launch_bounds__(NTHREADS)
void qlayer_fused(const float* __restrict__ x,
                  const float* __restrict__ qw,
                  const float* __restrict__ Wq,
                  const float* __restrict__ bq,
                  const float* __restrict__ Wc,
                  const float* __restrict__ bc,
                  float* __restrict__ out)
{
    __shared__ float4 sWqT[EDIM];      // 8 KB: [e] -> (Wq[0][e],Wq[1][e],Wq[2][e],Wq[3][e])
    __shared__ float4 sWcT[NQ][E4];    // 8 KB: Wc transposed [q][e4]
    __shared__ float4 sbc4[E4];        // 2 KB
    __shared__ float2 sdiag[NL][DIM];  // fused CRZ-ring diagonal
    __shared__ float2 srys[NL][NQ];
    __shared__ float  sbq[NQ];

    const int tid  = threadIdx.x;
    const int lane = tid & 31;
    const int warp = tid >> 5;

    // ---- Stage weights / constants (once per block) ----
    for (int e = tid; e < EDIM; e += NTHREADS)
        sWqT[e] = make_float4(Wq[e], Wq[EDIM+e], Wq[2*EDIM+e], Wq[3*EDIM+e]);
    {
        float* f = (float*)sWcT;
        for (int e = tid; e < EDIM; e += NTHREADS) {
            float4 r = ((const float4*)Wc)[e];
            f[0*EDIM+e] = r.x; f[1*EDIM+e] = r.y;
            f[2*EDIM+e] = r.z; f[3*EDIM+e] = r.w;
        }
    }
    for (int i = tid; i < E4; i += NTHREADS)
        sbc4[i] = ((const float4*)bc)[i];
    if (tid < NQ) sbq[tid] = bq[tid];

    if (tid < NL*DIM) {                // combined CRZ-ring diagonal
        int l = tid >> 4, k = tid & 15;
        float ang = 0.f;
        #pragma unroll
        for (int i = 0; i < NQ; i++) {
            int cb = (k >> (NQ-1-i)) & 1;
            int tb = (k >> (NQ-1-((i+1)&(NQ-1)))) & 1;
            if (cb) ang += 0.5f * qw[l*2*NQ + i] * (float)(2*tb - 1);
        }
        float sn, cs; sincosf(ang, &sn, &cs);
        sdiag[l][k] = make_float2(cs, sn);
    }
    if (tid >= 32 && tid < 32 + NL*NQ) {
        int t = tid - 32, l = t >> 2, i = t & 3;
        float sn, cs; sincosf(0.5f * qw[l*2*NQ + NQ + i], &sn, &cs);
        srys[l][i] = make_float2(cs, sn);
    }
    __syncthreads();

    const float bq0 = sbq[0], bq1 = sbq[1], bq2 = sbq[2], bq3 = sbq[3];
    const float4* __restrict__ x4 = (const float4*)x;
    float4* __restrict__ out4 = (float4*)out;
    const ulonglong2* __restrict__ wT  = (const ulonglong2*)sWqT;

    const int gwid   = blockIdx.x * NWARPS + warp;
    const int stride = GRID * NWARPS;          // 2368

    float4 xbuf[16];                   // 4 tokens x 4 chunks: pipeline buffer

    // ---- Prologue: load first tile ----
    int tile = gwid;
    if (tile < NTILES) {
        const size_t base = (size_t)tile * TOK_PER_TILE * E4 + lane;
        #pragma unroll
        for (int t = 0; t < 4; t++)
            #pragma unroll
            for (int c = 0; c < 4; c++)
                xbuf[t*4+c] = __ldcs(&x4[base + (size_t)t*E4 + c*32]);
    }

    #pragma unroll 1
    for (; tile < NTILES; tile += stride) {
        // ---- Consume buffer: packed partial dot products (frees xbuf) ----
        ull acc01[4], acc23[4];
        #pragma unroll
        for (int t = 0; t < 4; t++) { acc01[t] = pack2(0.f, 0.f); acc23[t] = pack2(0.f, 0.f); }

        #pragma unroll
        for (int c = 0; c < 4; c++) {
            const int e0 = (c*32 + lane)*4;            // scalar element base
            const ulonglong2 w0 = wT[e0+0], w1 = wT[e0+1];
            const ulonglong2 w2 = wT[e0+2], w3 = wT[e0+3];
            #pragma unroll
            for (int t = 0; t < 4; t++) {
                float4 xv = xbuf[t*4+c];
                ull dx = dup2(xv.x), dy = dup2(xv.y), dz = dup2(xv.z), dw = dup2(xv.w);
                acc01[t] = ffma2(dx, w0.x, acc01[t]);  acc23[t] = ffma2(dx, w0.y, acc23[t]);
                acc01[t] = ffma2(dy, w1.x, acc01[t]);  acc23[t] = ffma2(dy, w1.y, acc23[t]);
                acc01[t] = ffma2(dz, w2.x, acc01[t]);  acc23[t] = ffma2(dz, w2.y, acc23[t]);
                acc01[t] = ffma2(dw, w3.x, acc01[t]);  acc23[t] = ffma2(dw, w3.y, acc23[t]);
            }
        }

        // ---- Prefetch next tile NOW (in flight during shfl+circuit+store) ----
        const int nxt = tile + stride;
        if (nxt < NTILES) {
            const size_t base = (size_t)nxt * TOK_PER_TILE * E4 + lane;
            #pragma unroll
            for (int t = 0; t < 4; t++)
                #pragma unroll
                for (int c = 0; c < 4; c++)
                    xbuf[t*4+c] = __ldcs(&x4[base + (size_t)t*E4 + c*32]);
        }

        // ---- Unpack accumulators, tree reduction: 16 -> 1 per lane ----
        float v16[16];
        #pragma unroll
        for (int t = 0; t < 4; t++) {
            unpack2(acc01[t], v16[4*t+0], v16[4*t+1]);
            unpack2(acc23[t], v16[4*t+2], v16[4*t+3]);
        }
        float v8[8];
        {
            const bool hi = (lane & 16) != 0;
            #pragma unroll
            for (int i = 0; i < 8; i++) {
                float mine = hi ? v16[i+8] : v16[i];
                float send = hi ? v16[i]   : v16[i+8];
                v8[i] = mine + __shfl_xor_sync(0xffffffffu, send, 16);
            }
        }
        float v4[4];
        {
            const bool hi = (lane & 8) != 0;
            #pragma unroll
            for (int i = 0; i < 4; i++) {
                float mine = hi ? v8[i+4] : v8[i];
                float send = hi ? v8[i]   : v8[i+4];
                v4[i] = mine + __shfl_xor_sync(0xffffffffu, send, 8);
            }
        }
        float v2[2];
        {
            const bool hi = (lane & 4) != 0;
            #pragma unroll
            for (int i = 0; i < 2; i++) {
                float m2 = hi ? v4[i+2] : v4[i];
                float s2 = hi ? v4[i]   : v4[i+2];
                v2[i] = m2 + __shfl_xor_sync(0xffffffffu, s2, 4);
            }
        }
        float v1;
        {
            const bool hi = (lane & 2) != 0;
            float mine = hi ? v2[1] : v2[0];
            float send = hi ? v2[0] : v2[1];
            v1 = mine + __shfl_xor_sync(0xffffffffu, send, 2);
        }
        v1 += __shfl_xor_sync(0xffffffffu, v1, 1);
        // lane L holds (t = L>>3, q = 2*((L>>2)&1)+((L>>1)&1)); gather tokens -> lanes 0..3
        const int tl = lane & 3;
        float gx  = __shfl_sync(0xffffffffu, v1, 8*tl + 0);
        float gy  = __shfl_sync(0xffffffffu, v1, 8*tl + 2);
        float gz  = __shfl_sync(0xffffffffu, v1, 8*tl + 4);
        float gw_ = __shfl_sync(0xffffffffu, v1, 8*tl + 6);

        // ---- Circuit on lanes 0..3 (one token per lane) ----
        float z0 = 0.f, z1 = 0.f, z2 = 0.f, z3 = 0.f;
        if (lane < TOK_PER_TILE) {
            float c_[4], s_[4];
            __sincosf(0.5f*(gx + bq0),  &s_[0], &c_[0]);
            __sincosf(0.5f*(gy + bq1),  &s_[1], &c_[1]);
            __sincosf(0.5f*(gz + bq2),  &s_[2], &c_[2]);
            __sincosf(0.5f*(gw_ + bq3), &s_[3], &c_[3]);

            float2 st[DIM];
            #pragma unroll
            for (int k = 0; k < DIM; k++) {
                float m = 1.f; int p = 0;
                #pragma unroll
                for (int w = 0; w < NQ; w++) {
                    if ((k >> (NQ-1-w)) & 1) { m *= s_[w]; p++; }
                    else                     { m *= c_[w]; }
                }
                float re, im;
                switch (p & 3) {
                    case 0:  re =  m; im = 0.f; break;
                    case 1:  re = 0.f; im = -m; break;
                    case 2:  re = -m; im = 0.f; break;
                    default: re = 0.f; im =  m; break;
                }
                st[k] = make_float2(re, im);
            }

            #pragma unroll
            for (int l = 0; l < NL; l++) {
                #pragma unroll
                for (int k = 0; k < DIM; k++) {
                    float2 d = sdiag[l][k];
                    float re = st[k].x*d.x - st[k].y*d.y;
                    float im = st[k].x*d.y + st[k].y*d.x;
                    st[k].x = re; st[k].y = im;
                }
                #pragma unroll
                for (int i = 0; i < NQ; i++) {
                    float2 cs = srys[l][i];
                    const int S = 1 << (NQ-1-i);
                    #pragma unroll
                    for (int k = 0; k < DIM; k++) {
                        if (k & S) continue;
                        float2 a0 = st[k], a1 = st[k|S];
                        st[k].x   = cs.x*a0.x - cs.y*a1.x;
                        st[k].y   = cs.x*a0.y - cs.y*a1.y;
                        st[k|S].x = cs.y*a0.x + cs.x*a1.x;
                        st[k|S].y = cs.y*a0.y + cs.x*a1.y;
                    }
                }
            }

            #pragma unroll
            for (int k = 0; k < DIM; k++) {
                float p = st[k].x*st[k].x + st[k].y*st[k].y;
                z0 += (k & 8) ? -p : p;
                z1 += (k & 4) ? -p : p;
                z2 += (k & 2) ? -p : p;
                z3 += (k & 1) ? -p : p;
            }
        }

        // ---- Broadcast q_out once (16 SHFL) ----
        float qx[4], qy[4], qz[4], qe[4];
        #pragma unroll
        for (int m = 0; m < TOK_PER_TILE; m++) {
            qx[m] = __shfl_sync(0xffffffffu, z0, m);
            qy[m] = __shfl_sync(0xffffffffu, z1, m);
            qz[m] = __shfl_sync(0xffffffffu, z2, m);
            qe[m] = __shfl_sync(0xffffffffu, z3, m);
        }

        // ---- Phase 3: packed out = q_out . Wc^T + bc ----
        const size_t obase = (size_t)tile * TOK_PER_TILE * E4;
        #pragma unroll
        for (int c = 0; c < 4; c++) {
            const int e4 = c*32 + lane;
            const ulonglong2 w0 = ((const ulonglong2*)sWcT[0])[e4];
            const ulonglong2 w1 = ((const ulonglong2*)sWcT[1])[e4];
            const ulonglong2 w2 = ((const ulonglong2*)sWcT[2])[e4];
            const ulonglong2 w3 = ((const ulonglong2*)sWcT[3])[e4];
            const ulonglong2 bb = ((const ulonglong2*)sbc4)[e4];
            #pragma unroll
            for (int m = 0; m < TOK_PER_TILE; m++) {
                ull dqx = dup2(qx[m]), dqy = dup2(qy[m]);
                ull dqz = dup2(qz[m]), dqe = dup2(qe[m]);
                ull axy = bb.x, azw = bb.y;
                axy = ffma2(dqx, w0.x, axy);  azw = ffma2(dqx, w0.y, azw);
                axy = ffma2(dqy, w1.x, axy);  azw = ffma2(dqy, w1.y, azw);
                axy = ffma2(dqz, w2.x, axy);  azw = ffma2(dqz, w2.y, azw);
                axy = ffma2(dqe, w3.x, axy);  azw = ffma2(dqe, w3.y, azw);
                stcs2x64(&out4[obase + (size_t)m*E4 + e4], axy, azw);
            }
        }
    }
}

extern "C" void kernel_launch(void* const* d_in, const int* in_sizes, int n_in,
                              void* d_out, int out_size) {
    const float* x  = (const float*)d_in[0];
    const float* qw = (const float*)d_in[1];
    const float* Wq = (const float*)d_in[2];
    const float* bq = (const float*)d_in[3];
    const float* Wc = (const float*)d_in[4];
    const float* bc = (const float*)d_in[5];
    float* out = (float*)d_out;

    qlayer_fused<<<GRID, NTHREADS>>>(x, qw, Wq, bq, Wc, bc, out);
}